// round 1
// baseline (speedup 1.0000x reference)
#include <cuda_runtime.h>

typedef unsigned long long ull;

#define N_NODES 50000
#define N_EDGES 800000

// ---------- fp32x2 packed math (sm_103a; ptxas won't auto-fuse) ----------
__device__ __forceinline__ ull pack2(float a, float b){
    ull r; asm("mov.b64 %0,{%1,%2};" : "=l"(r) : "f"(a), "f"(b)); return r;
}
__device__ __forceinline__ void unpack2(ull v, float& a, float& b){
    asm("mov.b64 {%0,%1},%2;" : "=f"(a), "=f"(b) : "l"(v));
}
__device__ __forceinline__ ull fma2(ull a, ull b, ull c){
    ull d; asm("fma.rn.f32x2 %0,%1,%2,%3;" : "=l"(d) : "l"(a), "l"(b), "l"(c)); return d;
}
__device__ __forceinline__ ull mul2(ull a, ull b){
    ull d; asm("mul.rn.f32x2 %0,%1,%2;" : "=l"(d) : "l"(a), "l"(b)); return d;
}
__device__ __forceinline__ ull add2(ull a, ull b){
    ull d; asm("add.rn.f32x2 %0,%1,%2;" : "=l"(d) : "l"(a), "l"(b)); return d;
}
// vector reduction (no return) — avoids dependence on CUDA-header float4 atomicAdd overload
__device__ __forceinline__ void redAdd4(float4* addr, float4 v){
    asm volatile("red.global.add.v4.f32 [%0], {%1,%2,%3,%4};"
                 :: "l"(addr), "f"(v.x), "f"(v.y), "f"(v.z), "f"(v.w) : "memory");
}

// ---------- scratch (static device globals; no allocation allowed) ----------
__device__ __align__(256) float g_h0[(size_t)N_NODES * 128];
__device__ __align__(256) float g_h1[(size_t)N_NODES * 128];
__device__ __align__(256) float g_acch[(size_t)N_NODES * 128];
__device__ __align__(256) float g_accr[(size_t)N_NODES * 32];
__device__ __align__(256) float g_deg[N_NODES];
__device__ __align__(256) float g_invdeg[N_NODES];

// ---------- zeroing ----------
__global__ void zero3_kernel(float4* a, int na, float4* b, int nb, float4* c, int nc){
    int i = blockIdx.x * blockDim.x + threadIdx.x;
    int stride = gridDim.x * blockDim.x;
    float4 z = make_float4(0.f, 0.f, 0.f, 0.f);
    for (int k = i; k < na; k += stride) a[k] = z;
    for (int k = i; k < nb; k += stride) b[k] = z;
    if (c) for (int k = i; k < nc; k += stride) c[k] = z;
}

// ---------- degree ----------
__global__ void deg_kernel(const int* __restrict__ ei, float* __restrict__ deg){
    int i = blockIdx.x * blockDim.x + threadIdx.x;
    int stride = gridDim.x * blockDim.x;
    for (int e = i; e < N_EDGES; e += stride)
        atomicAdd(&deg[__ldg(&ei[N_EDGES + e])], 1.0f);
}

__global__ void invdeg_kernel(const float* __restrict__ deg, float* __restrict__ inv){
    int i = blockIdx.x * blockDim.x + threadIdx.x;
    if (i < N_NODES){
        float d = deg[i];
        inv[i] = d > 0.f ? 1.0f / d : 0.f;
    }
}

// ---------- edge aggregation: acc_h[dst] += h[src]; acc_r[dst] += rel_emb[rel] ----------
__global__ void edge_pass_kernel(const int* __restrict__ ei, const int* __restrict__ er,
                                 const float4* __restrict__ h4, const float4* __restrict__ rel4,
                                 float4* __restrict__ acch4, float4* __restrict__ accr4){
    int t = blockIdx.x * blockDim.x + threadIdx.x;
    int lane = t & 31;
    int warp = t >> 5;
    int nwarp = (gridDim.x * blockDim.x) >> 5;
    for (int e = warp; e < N_EDGES; e += nwarp){
        int src = __ldg(&ei[e]);
        int dst = __ldg(&ei[N_EDGES + e]);
        float4 v = __ldg(&h4[(size_t)src * 32 + lane]);
        redAdd4(&acch4[(size_t)dst * 32 + lane], v);
        if (lane < 8){
            int r = __ldg(&er[e]);
            float4 rv = __ldg(&rel4[(size_t)r * 8 + lane]);
            redAdd4(&accr4[(size_t)dst * 8 + lane], rv);
        }
    }
}

// ---------- input projection: h = relu([x, label_emb[label]] @ Win + b) ----------
#define IP_SMEM_FLOATS (20480 + 128 + 4 * 1288)
__global__ __launch_bounds__(512, 1)
void input_proj_kernel(const float* __restrict__ x, const int* __restrict__ label,
                       const float* __restrict__ label_emb, const float* __restrict__ Win,
                       const float* __restrict__ bin, float* __restrict__ hout){
    extern __shared__ float sm[];
    float* W_s = sm;                 // 160*128
    float* b_s = sm + 20480;         // 128
    int tid = threadIdx.x;
    int group = tid >> 7;
    int j = tid & 127;
    float* xs = sm + 20608 + group * 1288;  // 160*8 staging (+pad)

    for (int i = tid; i < 20480; i += 512) W_s[i] = Win[i];
    if (tid < 128) b_s[tid] = bin[tid];

    int gid = blockIdx.x * 4 + group;
    int ngroups = gridDim.x * 4;
    const int NBATCH = N_NODES / 8;  // 6250
    int iters = (NBATCH + ngroups - 1) / ngroups;

    for (int it = 0; it < iters; it++){
        int bi = gid + it * ngroups;
        bool valid = bi < NBATCH;
        int node0 = bi * 8;
        __syncthreads();
        if (valid){
            #pragma unroll
            for (int m = 0; m < 8; m++){
                int node = node0 + m;
                xs[j * 8 + m] = x[(size_t)node * 128 + j];
                if (j < 32){
                    int lab = __ldg(&label[node]);
                    xs[(128 + j) * 8 + m] = label_emb[(size_t)lab * 32 + j];
                }
            }
        }
        __syncthreads();
        if (valid){
            ull c0 = 0, c1 = 0, c2 = 0, c3 = 0;
            const ulonglong2* X2 = (const ulonglong2*)xs;
            #pragma unroll 4
            for (int k = 0; k < 160; k++){
                float w = W_s[k * 128 + j];
                ull w2 = pack2(w, w);
                ulonglong2 p = X2[2 * k], q = X2[2 * k + 1];
                c0 = fma2(w2, p.x, c0); c1 = fma2(w2, p.y, c1);
                c2 = fma2(w2, q.x, c2); c3 = fma2(w2, q.y, c3);
            }
            float bb = b_s[j];
            float v[8];
            unpack2(c0, v[0], v[1]); unpack2(c1, v[2], v[3]);
            unpack2(c2, v[4], v[5]); unpack2(c3, v[6], v[7]);
            #pragma unroll
            for (int m = 0; m < 8; m++)
                hout[(size_t)(node0 + m) * 128 + j] = fmaxf(v[m] + bb, 0.f);
        }
    }
}

// ---------- node update: h' = LN(relu(h@Ws + b + (acc_h@Wn + acc_r@Wr)*inv_deg)) ----------
#define NU_WOFF 37248
#define NU_GRPF 2376
#define NU_SMEM_FLOATS (NU_WOFF + 4 * NU_GRPF)
__global__ __launch_bounds__(512, 1)
void node_update_kernel(const float* __restrict__ hin, const float* __restrict__ acch,
                        const float* __restrict__ accr, const float* __restrict__ invdeg,
                        const float* __restrict__ Wn, const float* __restrict__ Wr,
                        const float* __restrict__ Wself, const float* __restrict__ bias,
                        const float* __restrict__ lng, const float* __restrict__ lnb,
                        float* __restrict__ hout){
    extern __shared__ float sm[];
    float* Wn_s   = sm;             // 16384
    float* Wr_s   = sm + 16384;     // 4096
    float* Ws_s   = sm + 20480;     // 16384
    float* bias_s = sm + 36864;     // 128
    float* g_s    = sm + 36992;     // 128
    float* b_s    = sm + 37120;     // 128
    int tid = threadIdx.x;
    int group = tid >> 7;
    int j = tid & 127;
    int lane = tid & 31;
    int wig = (tid & 127) >> 5;
    float* grp = sm + NU_WOFF + group * NU_GRPF;
    float* hs  = grp;          // 1024: hs[k][m]
    float* as_ = grp + 1024;   // 1024
    float* rs  = grp + 2048;   // 256
    float* idv = grp + 2304;   // 8
    float* red = grp + 2312;   // 64

    for (int i = tid; i < 16384; i += 512){ Wn_s[i] = Wn[i]; Ws_s[i] = Wself[i]; }
    for (int i = tid; i < 4096; i += 512) Wr_s[i] = Wr[i];
    if (tid < 128){ bias_s[tid] = bias[tid]; g_s[tid] = lng[tid]; b_s[tid] = lnb[tid]; }

    int gid = blockIdx.x * 4 + group;
    int ngroups = gridDim.x * 4;
    const int NBATCH = N_NODES / 8;  // 6250
    int iters = (NBATCH + ngroups - 1) / ngroups;

    for (int it = 0; it < iters; it++){
        int bi = gid + it * ngroups;
        bool valid = bi < NBATCH;
        int node0 = bi * 8;
        __syncthreads();
        if (valid){
            #pragma unroll
            for (int m = 0; m < 8; m++){
                int node = node0 + m;
                hs[j * 8 + m]  = hin[(size_t)node * 128 + j];
                as_[j * 8 + m] = acch[(size_t)node * 128 + j];
            }
            #pragma unroll
            for (int t2 = j * 2; t2 < j * 2 + 2; t2++)
                rs[t2] = accr[(size_t)(node0 + (t2 & 7)) * 32 + (t2 >> 3)];
            if (j < 8) idv[j] = invdeg[node0 + j];
        }
        __syncthreads();
        float v[8];
        if (valid){
            ull c0 = 0, c1 = 0, c2 = 0, c3 = 0;
            const ulonglong2* A2 = (const ulonglong2*)as_;
            #pragma unroll 4
            for (int k = 0; k < 128; k++){
                float w = Wn_s[k * 128 + j];
                ull w2 = pack2(w, w);
                ulonglong2 p = A2[2 * k], q = A2[2 * k + 1];
                c0 = fma2(w2, p.x, c0); c1 = fma2(w2, p.y, c1);
                c2 = fma2(w2, q.x, c2); c3 = fma2(w2, q.y, c3);
            }
            const ulonglong2* R2 = (const ulonglong2*)rs;
            #pragma unroll 4
            for (int k = 0; k < 32; k++){
                float w = Wr_s[k * 128 + j];
                ull w2 = pack2(w, w);
                ulonglong2 p = R2[2 * k], q = R2[2 * k + 1];
                c0 = fma2(w2, p.x, c0); c1 = fma2(w2, p.y, c1);
                c2 = fma2(w2, q.x, c2); c3 = fma2(w2, q.y, c3);
            }
            ull d0 = pack2(idv[0], idv[1]);
            ull d1 = pack2(idv[2], idv[3]);
            ull d2 = pack2(idv[4], idv[5]);
            ull d3 = pack2(idv[6], idv[7]);
            c0 = mul2(c0, d0); c1 = mul2(c1, d1); c2 = mul2(c2, d2); c3 = mul2(c3, d3);
            const ulonglong2* H2 = (const ulonglong2*)hs;
            #pragma unroll 4
            for (int k = 0; k < 128; k++){
                float w = Ws_s[k * 128 + j];
                ull w2 = pack2(w, w);
                ulonglong2 p = H2[2 * k], q = H2[2 * k + 1];
                c0 = fma2(w2, p.x, c0); c1 = fma2(w2, p.y, c1);
                c2 = fma2(w2, q.x, c2); c3 = fma2(w2, q.y, c3);
            }
            float bb = bias_s[j];
            ull b2 = pack2(bb, bb);
            c0 = add2(c0, b2); c1 = add2(c1, b2); c2 = add2(c2, b2); c3 = add2(c3, b2);
            unpack2(c0, v[0], v[1]); unpack2(c1, v[2], v[3]);
            unpack2(c2, v[4], v[5]); unpack2(c3, v[6], v[7]);
            // relu + warp-level partial reductions for LN (over the 128 j's)
            #pragma unroll
            for (int m = 0; m < 8; m++){
                v[m] = fmaxf(v[m], 0.f);
                float s = v[m], q2 = v[m] * v[m];
                #pragma unroll
                for (int o = 16; o > 0; o >>= 1){
                    s  += __shfl_xor_sync(0xffffffffu, s, o);
                    q2 += __shfl_xor_sync(0xffffffffu, q2, o);
                }
                if (lane == 0){ red[wig * 16 + m] = s; red[wig * 16 + 8 + m] = q2; }
            }
        }
        __syncthreads();
        if (valid){
            #pragma unroll
            for (int m = 0; m < 8; m++){
                float s  = red[m] + red[16 + m] + red[32 + m] + red[48 + m];
                float q2 = red[8 + m] + red[24 + m] + red[40 + m] + red[56 + m];
                float mean = s * (1.0f / 128.0f);
                float var = fmaxf(q2 * (1.0f / 128.0f) - mean * mean, 0.f);
                float rstd = rsqrtf(var + 1e-5f);
                hout[(size_t)(node0 + m) * 128 + j] = (v[m] - mean) * rstd * g_s[j] + b_s[j];
            }
        }
    }
}

extern "C" void kernel_launch(void* const* d_in, const int* in_sizes, int n_in,
                              void* d_out, int out_size){
    const float* x         = (const float*)d_in[0];
    const int*   label     = (const int*)d_in[1];
    const int*   ei        = (const int*)d_in[2];
    const int*   er        = (const int*)d_in[3];
    const float* label_emb = (const float*)d_in[4];
    const float* in_w      = (const float*)d_in[5];
    const float* in_b      = (const float*)d_in[6];
    const float* rel_emb   = (const float*)d_in[7];
    const float* wn        = (const float*)d_in[8];
    const float* wself     = (const float*)d_in[9];
    const float* bself     = (const float*)d_in[10];
    const float* wr        = (const float*)d_in[11];
    const float* lng       = (const float*)d_in[12];
    const float* lnb       = (const float*)d_in[13];

    float *h0, *h1, *acch, *accr, *deg, *invdeg;
    cudaGetSymbolAddress((void**)&h0, g_h0);
    cudaGetSymbolAddress((void**)&h1, g_h1);
    cudaGetSymbolAddress((void**)&acch, g_acch);
    cudaGetSymbolAddress((void**)&accr, g_accr);
    cudaGetSymbolAddress((void**)&deg, g_deg);
    cudaGetSymbolAddress((void**)&invdeg, g_invdeg);

    int ip_smem = IP_SMEM_FLOATS * 4;
    int nu_smem = NU_SMEM_FLOATS * 4;
    cudaFuncSetAttribute(input_proj_kernel, cudaFuncAttributeMaxDynamicSharedMemorySize, ip_smem);
    cudaFuncSetAttribute(node_update_kernel, cudaFuncAttributeMaxDynamicSharedMemorySize, nu_smem);

    // zero deg + accumulators
    zero3_kernel<<<512, 256>>>((float4*)deg, N_NODES / 4,
                               (float4*)acch, N_NODES * 32,
                               (float4*)accr, N_NODES * 8);
    deg_kernel<<<1024, 256>>>(ei, deg);
    input_proj_kernel<<<148, 512, ip_smem>>>(x, label, label_emb, in_w, in_b, h0);
    invdeg_kernel<<<(N_NODES + 255) / 256, 256>>>(deg, invdeg);

    // layer 0
    edge_pass_kernel<<<2368, 256>>>(ei, er, (const float4*)h0, (const float4*)rel_emb,
                                    (float4*)acch, (float4*)accr);
    node_update_kernel<<<148, 512, nu_smem>>>(h0, acch, accr, invdeg,
                                              wn, wr, wself, bself, lng, lnb, h1);

    // layer 1
    zero3_kernel<<<512, 256>>>((float4*)acch, N_NODES * 32,
                               (float4*)accr, N_NODES * 8, nullptr, 0);
    edge_pass_kernel<<<2368, 256>>>(ei, er, (const float4*)h1,
                                    (const float4*)(rel_emb + 1024 * 32),
                                    (float4*)acch, (float4*)accr);
    node_update_kernel<<<148, 512, nu_smem>>>(h1, acch, accr, invdeg,
                                              wn + 16384, wr + 4096, wself + 16384,
                                              bself + 128, lng + 128, lnb + 128,
                                              (float*)d_out);
}

// round 2
// speedup vs baseline: 1.0390x; 1.0390x over previous
#include <cuda_runtime.h>

typedef unsigned long long ull;

#define N_NODES 50000
#define N_EDGES 800000

// ---------- fp32x2 packed math (sm_103a; ptxas won't auto-fuse) ----------
__device__ __forceinline__ ull pack2(float a, float b){
    ull r; asm("mov.b64 %0,{%1,%2};" : "=l"(r) : "f"(a), "f"(b)); return r;
}
__device__ __forceinline__ void unpack2(ull v, float& a, float& b){
    asm("mov.b64 {%0,%1},%2;" : "=f"(a), "=f"(b) : "l"(v));
}
__device__ __forceinline__ ull fma2(ull a, ull b, ull c){
    ull d; asm("fma.rn.f32x2 %0,%1,%2,%3;" : "=l"(d) : "l"(a), "l"(b), "l"(c)); return d;
}
__device__ __forceinline__ ull add2(ull a, ull b){
    ull d; asm("add.rn.f32x2 %0,%1,%2;" : "=l"(d) : "l"(a), "l"(b)); return d;
}

// ---------- scratch (static device globals; no allocation allowed) ----------
__device__ __align__(256) float g_h0[(size_t)N_NODES * 128];
__device__ __align__(256) float g_h1[(size_t)N_NODES * 128];
__device__ __align__(256) float g_acch[(size_t)N_NODES * 128];
__device__ __align__(256) float g_accr[(size_t)N_NODES * 32];
__device__ __align__(256) int   g_deg[N_NODES];
__device__ __align__(256) float g_invdeg[N_NODES];
__device__ __align__(256) int   g_row[N_NODES + 1];
__device__ __align__(256) int   g_cursor[N_NODES];
__device__ __align__(256) int2  g_edges[N_EDGES];   // (src, rel) sorted by dst

// ---------- CSR build ----------
__global__ void zero_deg_kernel(int* __restrict__ deg){
    int i = blockIdx.x * blockDim.x + threadIdx.x;
    if (i < N_NODES) deg[i] = 0;
}

__global__ void deg_kernel(const int* __restrict__ ei, int* __restrict__ deg){
    int i = blockIdx.x * blockDim.x + threadIdx.x;
    int stride = gridDim.x * blockDim.x;
    for (int e = i; e < N_EDGES; e += stride)
        atomicAdd(&deg[__ldg(&ei[N_EDGES + e])], 1);
}

// single-block exclusive scan over 50000 degrees -> row[], cursor[]
__global__ __launch_bounds__(1024, 1)
void scan_kernel(const int* __restrict__ deg, int* __restrict__ row,
                 int* __restrict__ cursor, float* __restrict__ invdeg){
    __shared__ int part[1024];
    const int CH = (N_NODES + 1023) / 1024;   // 49
    int t = threadIdx.x;
    int base = t * CH;
    int s = 0;
    #pragma unroll 4
    for (int i = 0; i < CH; i++){
        int idx = base + i;
        if (idx < N_NODES) s += deg[idx];
    }
    part[t] = s;
    __syncthreads();
    for (int o = 1; o < 1024; o <<= 1){
        int add = (t >= o) ? part[t - o] : 0;
        __syncthreads();
        part[t] += add;
        __syncthreads();
    }
    int run = part[t] - s;   // exclusive prefix
    for (int i = 0; i < CH; i++){
        int idx = base + i;
        if (idx < N_NODES){
            int d = deg[idx];
            row[idx] = run;
            cursor[idx] = run;
            invdeg[idx] = d > 0 ? 1.0f / (float)d : 0.f;
            run += d;
        }
    }
    if (t == 1023) row[N_NODES] = run;
}

__global__ void scatter_kernel(const int* __restrict__ ei, const int* __restrict__ er,
                               int* __restrict__ cursor, int2* __restrict__ es){
    int i = blockIdx.x * blockDim.x + threadIdx.x;
    int stride = gridDim.x * blockDim.x;
    for (int e = i; e < N_EDGES; e += stride){
        int dst = __ldg(&ei[N_EDGES + e]);
        int pos = atomicAdd(&cursor[dst], 1);
        es[pos] = make_int2(__ldg(&ei[e]), __ldg(&er[e]));
    }
}

// ---------- edge aggregation (gather, atomic-free): acc = (sum h[src]) * invdeg ----------
__global__ __launch_bounds__(256)
void gather_kernel(const int* __restrict__ row, const int2* __restrict__ es,
                   const float* __restrict__ invdeg,
                   const float4* __restrict__ h4, const float4* __restrict__ rel4,
                   float4* __restrict__ acch4, float4* __restrict__ accr4){
    int w = (blockIdx.x * blockDim.x + threadIdx.x) >> 5;
    int lane = threadIdx.x & 31;
    if (w >= N_NODES) return;
    int s = __ldg(&row[w]);
    int e = __ldg(&row[w + 1]);
    float4 a = make_float4(0.f, 0.f, 0.f, 0.f);
    float4 r = make_float4(0.f, 0.f, 0.f, 0.f);
    #pragma unroll 2
    for (int i = s; i < e; i++){
        int2 m = __ldg(&es[i]);                       // lane-broadcast, L1 hit
        float4 v = __ldg(&h4[(size_t)m.x * 32 + lane]);
        a.x += v.x; a.y += v.y; a.z += v.z; a.w += v.w;
        if (lane < 8){
            float4 rv = __ldg(&rel4[(size_t)m.y * 8 + lane]);
            r.x += rv.x; r.y += rv.y; r.z += rv.z; r.w += rv.w;
        }
    }
    float inv = __ldg(&invdeg[w]);
    a.x *= inv; a.y *= inv; a.z *= inv; a.w *= inv;
    acch4[(size_t)w * 32 + lane] = a;
    if (lane < 8){
        r.x *= inv; r.y *= inv; r.z *= inv; r.w *= inv;
        accr4[(size_t)w * 8 + lane] = r;
    }
}

// ---------- input projection: h = relu([x, label_emb[label]] @ Win + b) ----------
#define IP_SMEM_FLOATS (20480 + 128 + 4 * 1288)
__global__ __launch_bounds__(512, 1)
void input_proj_kernel(const float* __restrict__ x, const int* __restrict__ label,
                       const float* __restrict__ label_emb, const float* __restrict__ Win,
                       const float* __restrict__ bin, float* __restrict__ hout){
    extern __shared__ float sm[];
    float* W_s = sm;                 // 160*128
    float* b_s = sm + 20480;         // 128
    int tid = threadIdx.x;
    int group = tid >> 7;
    int j = tid & 127;
    float* xs = sm + 20608 + group * 1288;  // 160*8 staging (+pad)

    for (int i = tid; i < 20480; i += 512) W_s[i] = Win[i];
    if (tid < 128) b_s[tid] = bin[tid];

    int gid = blockIdx.x * 4 + group;
    int ngroups = gridDim.x * 4;
    const int NBATCH = N_NODES / 8;  // 6250
    int iters = (NBATCH + ngroups - 1) / ngroups;

    for (int it = 0; it < iters; it++){
        int bi = gid + it * ngroups;
        bool valid = bi < NBATCH;
        int node0 = bi * 8;
        __syncthreads();
        if (valid){
            #pragma unroll
            for (int m = 0; m < 8; m++){
                int node = node0 + m;
                xs[j * 8 + m] = x[(size_t)node * 128 + j];
                if (j < 32){
                    int lab = __ldg(&label[node]);
                    xs[(128 + j) * 8 + m] = label_emb[(size_t)lab * 32 + j];
                }
            }
        }
        __syncthreads();
        if (valid){
            ull c0 = 0, c1 = 0, c2 = 0, c3 = 0;
            const ulonglong2* X2 = (const ulonglong2*)xs;
            #pragma unroll 4
            for (int k = 0; k < 160; k++){
                float w = W_s[k * 128 + j];
                ull w2 = pack2(w, w);
                ulonglong2 p = X2[2 * k], q = X2[2 * k + 1];
                c0 = fma2(w2, p.x, c0); c1 = fma2(w2, p.y, c1);
                c2 = fma2(w2, q.x, c2); c3 = fma2(w2, q.y, c3);
            }
            float bb = b_s[j];
            float v[8];
            unpack2(c0, v[0], v[1]); unpack2(c1, v[2], v[3]);
            unpack2(c2, v[4], v[5]); unpack2(c3, v[6], v[7]);
            #pragma unroll
            for (int m = 0; m < 8; m++)
                hout[(size_t)(node0 + m) * 128 + j] = fmaxf(v[m] + bb, 0.f);
        }
    }
}

// ---------- node update: h' = LN(relu(h@Ws + b + acc_h@Wn + acc_r@Wr)) ----------
// (inv_deg already folded into acc_h / acc_r by gather_kernel)
#define NU_WOFF 37248
#define NU_GRPF 2376
#define NU_SMEM_FLOATS (NU_WOFF + 4 * NU_GRPF)
__global__ __launch_bounds__(512, 1)
void node_update_kernel(const float* __restrict__ hin, const float* __restrict__ acch,
                        const float* __restrict__ accr,
                        const float* __restrict__ Wn, const float* __restrict__ Wr,
                        const float* __restrict__ Wself, const float* __restrict__ bias,
                        const float* __restrict__ lng, const float* __restrict__ lnb,
                        float* __restrict__ hout){
    extern __shared__ float sm[];
    float* Wn_s   = sm;             // 16384
    float* Wr_s   = sm + 16384;     // 4096
    float* Ws_s   = sm + 20480;     // 16384
    float* bias_s = sm + 36864;     // 128
    float* g_s    = sm + 36992;     // 128
    float* b_s    = sm + 37120;     // 128
    int tid = threadIdx.x;
    int group = tid >> 7;
    int j = tid & 127;
    int lane = tid & 31;
    int wig = (tid & 127) >> 5;
    float* grp = sm + NU_WOFF + group * NU_GRPF;
    float* hs  = grp;          // 1024: hs[k][m]
    float* as_ = grp + 1024;   // 1024
    float* rs  = grp + 2048;   // 256
    float* red = grp + 2304;   // 64

    for (int i = tid; i < 16384; i += 512){ Wn_s[i] = Wn[i]; Ws_s[i] = Wself[i]; }
    for (int i = tid; i < 4096; i += 512) Wr_s[i] = Wr[i];
    if (tid < 128){ bias_s[tid] = bias[tid]; g_s[tid] = lng[tid]; b_s[tid] = lnb[tid]; }

    int gid = blockIdx.x * 4 + group;
    int ngroups = gridDim.x * 4;
    const int NBATCH = N_NODES / 8;  // 6250
    int iters = (NBATCH + ngroups - 1) / ngroups;

    for (int it = 0; it < iters; it++){
        int bi = gid + it * ngroups;
        bool valid = bi < NBATCH;
        int node0 = bi * 8;
        __syncthreads();
        if (valid){
            #pragma unroll
            for (int m = 0; m < 8; m++){
                int node = node0 + m;
                hs[j * 8 + m]  = hin[(size_t)node * 128 + j];
                as_[j * 8 + m] = acch[(size_t)node * 128 + j];
            }
            #pragma unroll
            for (int t2 = j * 2; t2 < j * 2 + 2; t2++)
                rs[t2] = accr[(size_t)(node0 + (t2 & 7)) * 32 + (t2 >> 3)];
        }
        __syncthreads();
        float v[8];
        if (valid){
            ull c0 = 0, c1 = 0, c2 = 0, c3 = 0;
            const ulonglong2* A2 = (const ulonglong2*)as_;
            #pragma unroll 4
            for (int k = 0; k < 128; k++){
                float w = Wn_s[k * 128 + j];
                ull w2 = pack2(w, w);
                ulonglong2 p = A2[2 * k], q = A2[2 * k + 1];
                c0 = fma2(w2, p.x, c0); c1 = fma2(w2, p.y, c1);
                c2 = fma2(w2, q.x, c2); c3 = fma2(w2, q.y, c3);
            }
            const ulonglong2* R2 = (const ulonglong2*)rs;
            #pragma unroll 4
            for (int k = 0; k < 32; k++){
                float w = Wr_s[k * 128 + j];
                ull w2 = pack2(w, w);
                ulonglong2 p = R2[2 * k], q = R2[2 * k + 1];
                c0 = fma2(w2, p.x, c0); c1 = fma2(w2, p.y, c1);
                c2 = fma2(w2, q.x, c2); c3 = fma2(w2, q.y, c3);
            }
            const ulonglong2* H2 = (const ulonglong2*)hs;
            #pragma unroll 4
            for (int k = 0; k < 128; k++){
                float w = Ws_s[k * 128 + j];
                ull w2 = pack2(w, w);
                ulonglong2 p = H2[2 * k], q = H2[2 * k + 1];
                c0 = fma2(w2, p.x, c0); c1 = fma2(w2, p.y, c1);
                c2 = fma2(w2, q.x, c2); c3 = fma2(w2, q.y, c3);
            }
            float bb = bias_s[j];
            ull b2 = pack2(bb, bb);
            c0 = add2(c0, b2); c1 = add2(c1, b2); c2 = add2(c2, b2); c3 = add2(c3, b2);
            unpack2(c0, v[0], v[1]); unpack2(c1, v[2], v[3]);
            unpack2(c2, v[4], v[5]); unpack2(c3, v[6], v[7]);
            #pragma unroll
            for (int m = 0; m < 8; m++){
                v[m] = fmaxf(v[m], 0.f);
                float s = v[m], q2 = v[m] * v[m];
                #pragma unroll
                for (int o = 16; o > 0; o >>= 1){
                    s  += __shfl_xor_sync(0xffffffffu, s, o);
                    q2 += __shfl_xor_sync(0xffffffffu, q2, o);
                }
                if (lane == 0){ red[wig * 16 + m] = s; red[wig * 16 + 8 + m] = q2; }
            }
        }
        __syncthreads();
        if (valid){
            #pragma unroll
            for (int m = 0; m < 8; m++){
                float s  = red[m] + red[16 + m] + red[32 + m] + red[48 + m];
                float q2 = red[8 + m] + red[24 + m] + red[40 + m] + red[56 + m];
                float mean = s * (1.0f / 128.0f);
                float var = fmaxf(q2 * (1.0f / 128.0f) - mean * mean, 0.f);
                float rstd = rsqrtf(var + 1e-5f);
                hout[(size_t)(node0 + m) * 128 + j] = (v[m] - mean) * rstd * g_s[j] + b_s[j];
            }
        }
    }
}

extern "C" void kernel_launch(void* const* d_in, const int* in_sizes, int n_in,
                              void* d_out, int out_size){
    const float* x         = (const float*)d_in[0];
    const int*   label     = (const int*)d_in[1];
    const int*   ei        = (const int*)d_in[2];
    const int*   er        = (const int*)d_in[3];
    const float* label_emb = (const float*)d_in[4];
    const float* in_w      = (const float*)d_in[5];
    const float* in_b      = (const float*)d_in[6];
    const float* rel_emb   = (const float*)d_in[7];
    const float* wn        = (const float*)d_in[8];
    const float* wself     = (const float*)d_in[9];
    const float* bself     = (const float*)d_in[10];
    const float* wr        = (const float*)d_in[11];
    const float* lng       = (const float*)d_in[12];
    const float* lnb       = (const float*)d_in[13];

    float *h0, *h1, *acch, *accr, *invdeg;
    int *deg, *row, *cursor;
    int2 *edges;
    cudaGetSymbolAddress((void**)&h0, g_h0);
    cudaGetSymbolAddress((void**)&h1, g_h1);
    cudaGetSymbolAddress((void**)&acch, g_acch);
    cudaGetSymbolAddress((void**)&accr, g_accr);
    cudaGetSymbolAddress((void**)&deg, g_deg);
    cudaGetSymbolAddress((void**)&invdeg, g_invdeg);
    cudaGetSymbolAddress((void**)&row, g_row);
    cudaGetSymbolAddress((void**)&cursor, g_cursor);
    cudaGetSymbolAddress((void**)&edges, g_edges);

    int ip_smem = IP_SMEM_FLOATS * 4;
    int nu_smem = NU_SMEM_FLOATS * 4;
    cudaFuncSetAttribute(input_proj_kernel, cudaFuncAttributeMaxDynamicSharedMemorySize, ip_smem);
    cudaFuncSetAttribute(node_update_kernel, cudaFuncAttributeMaxDynamicSharedMemorySize, nu_smem);

    // CSR build
    zero_deg_kernel<<<(N_NODES + 255) / 256, 256>>>(deg);
    deg_kernel<<<1024, 256>>>(ei, deg);
    scan_kernel<<<1, 1024>>>(deg, row, cursor, invdeg);
    scatter_kernel<<<1024, 256>>>(ei, er, cursor, edges);

    // input projection
    input_proj_kernel<<<148, 512, ip_smem>>>(x, label, label_emb, in_w, in_b, h0);

    // layer 0
    gather_kernel<<<(N_NODES * 32 + 255) / 256, 256>>>(row, edges, invdeg,
                                                       (const float4*)h0, (const float4*)rel_emb,
                                                       (float4*)acch, (float4*)accr);
    node_update_kernel<<<148, 512, nu_smem>>>(h0, acch, accr,
                                              wn, wr, wself, bself, lng, lnb, h1);

    // layer 1
    gather_kernel<<<(N_NODES * 32 + 255) / 256, 256>>>(row, edges, invdeg,
                                                       (const float4*)h1,
                                                       (const float4*)(rel_emb + 1024 * 32),
                                                       (float4*)acch, (float4*)accr);
    node_update_kernel<<<148, 512, nu_smem>>>(h1, acch, accr,
                                              wn + 16384, wr + 4096, wself + 16384,
                                              bself + 128, lng + 128, lnb + 128,
                                              (float*)d_out);
}

// round 5
// speedup vs baseline: 1.0459x; 1.0067x over previous
#include <cuda_runtime.h>

typedef unsigned long long ull;

#define N_NODES 50000
#define N_EDGES 800000
#define FULLMASK 0xffffffffu

// ---------- fp32x2 packed math (sm_103a; ptxas won't auto-fuse) ----------
__device__ __forceinline__ ull pack2(float a, float b){
    ull r; asm("mov.b64 %0,{%1,%2};" : "=l"(r) : "f"(a), "f"(b)); return r;
}
__device__ __forceinline__ void unpack2(ull v, float& a, float& b){
    asm("mov.b64 {%0,%1},%2;" : "=f"(a), "=f"(b) : "l"(v));
}
__device__ __forceinline__ ull fma2(ull a, ull b, ull c){
    ull d; asm("fma.rn.f32x2 %0,%1,%2,%3;" : "=l"(d) : "l"(a), "l"(b), "l"(c)); return d;
}
__device__ __forceinline__ ull add2(ull a, ull b){
    ull d; asm("add.rn.f32x2 %0,%1,%2;" : "=l"(d) : "l"(a), "l"(b)); return d;
}

// ---------- scratch (static device globals; no allocation allowed) ----------
__device__ __align__(256) float g_h0[(size_t)N_NODES * 128];
__device__ __align__(256) float g_h1[(size_t)N_NODES * 128];
__device__ __align__(256) float g_acch[(size_t)N_NODES * 128];
__device__ __align__(256) float g_accr[(size_t)N_NODES * 32];
__device__ __align__(256) int   g_deg[N_NODES];
__device__ __align__(256) float g_invdeg[N_NODES];
__device__ __align__(256) int   g_row[N_NODES + 1];
__device__ __align__(256) int   g_cursor[N_NODES];
__device__ __align__(256) int2  g_edges[N_EDGES];   // (src, rel) sorted by dst

// ---------- CSR build ----------
__global__ void zero_deg_kernel(int* __restrict__ deg){
    int i = blockIdx.x * blockDim.x + threadIdx.x;
    if (i < N_NODES) deg[i] = 0;
}

__global__ void deg_kernel(const int* __restrict__ ei, int* __restrict__ deg){
    int i = blockIdx.x * blockDim.x + threadIdx.x;
    int stride = gridDim.x * blockDim.x;
    for (int e = i; e < N_EDGES; e += stride)
        atomicAdd(&deg[__ldg(&ei[N_EDGES + e])], 1);
}

// single-block exclusive scan over 50000 degrees -> row[], cursor[]
__global__ __launch_bounds__(1024, 1)
void scan_kernel(const int* __restrict__ deg, int* __restrict__ row,
                 int* __restrict__ cursor, float* __restrict__ invdeg){
    __shared__ int part[1024];
    const int CH = (N_NODES + 1023) / 1024;   // 49
    int t = threadIdx.x;
    int base = t * CH;
    int s = 0;
    #pragma unroll 7
    for (int i = 0; i < CH; i++){
        int idx = base + i;
        if (idx < N_NODES) s += __ldg(&deg[idx]);
    }
    part[t] = s;
    __syncthreads();
    for (int o = 1; o < 1024; o <<= 1){
        int add = (t >= o) ? part[t - o] : 0;
        __syncthreads();
        part[t] += add;
        __syncthreads();
    }
    int run = part[t] - s;   // exclusive prefix
    for (int i = 0; i < CH; i++){
        int idx = base + i;
        if (idx < N_NODES){
            int d = __ldg(&deg[idx]);
            row[idx] = run;
            cursor[idx] = run;
            invdeg[idx] = d > 0 ? 1.0f / (float)d : 0.f;
            run += d;
        }
    }
    if (t == 1023) row[N_NODES] = run;
}

__global__ void scatter_kernel(const int* __restrict__ ei, const int* __restrict__ er,
                               int* __restrict__ cursor, int2* __restrict__ es){
    int i = blockIdx.x * blockDim.x + threadIdx.x;
    int stride = gridDim.x * blockDim.x;
    for (int e = i; e < N_EDGES; e += stride){
        int dst = __ldg(&ei[N_EDGES + e]);
        int pos = atomicAdd(&cursor[dst], 1);
        es[pos] = make_int2(__ldg(&ei[e]), __ldg(&er[e]));
    }
}

// ---------- edge aggregation (gather, atomic-free, deep MLP) ----------
// acc_h[w] = (sum_{e->w} h[src]) * invdeg[w];  acc_r[w] = (sum rel_emb[rel]) * invdeg[w]
__global__ __launch_bounds__(256)
void gather_kernel(const int* __restrict__ row, const int2* __restrict__ es,
                   const float* __restrict__ invdeg,
                   const float4* __restrict__ h4, const float* __restrict__ rel,
                   float4* __restrict__ acch4, float* __restrict__ accr){
    int w = (blockIdx.x * blockDim.x + threadIdx.x) >> 5;
    int lane = threadIdx.x & 31;
    if (w >= N_NODES) return;
    int s = __ldg(&row[w]);
    int e = __ldg(&row[w + 1]);
    float4 a = make_float4(0.f, 0.f, 0.f, 0.f);
    float ra = 0.f;
    for (int base = s; base < e; base += 32){
        int cnt = min(32, e - base);
        int2 m = make_int2(0, 0);
        if (lane < cnt) m = __ldg(&es[base + lane]);   // one coalesced meta load
        int i = 0;
        for (; i + 4 <= cnt; i += 4){
            int s0 = __shfl_sync(FULLMASK, m.x, i);
            int s1 = __shfl_sync(FULLMASK, m.x, i + 1);
            int s2 = __shfl_sync(FULLMASK, m.x, i + 2);
            int s3 = __shfl_sync(FULLMASK, m.x, i + 3);
            int r0 = __shfl_sync(FULLMASK, m.y, i);
            int r1 = __shfl_sync(FULLMASK, m.y, i + 1);
            int r2 = __shfl_sync(FULLMASK, m.y, i + 2);
            int r3 = __shfl_sync(FULLMASK, m.y, i + 3);
            // 8 independent loads in flight before any consume
            float4 v0 = __ldg(&h4[(size_t)s0 * 32 + lane]);
            float4 v1 = __ldg(&h4[(size_t)s1 * 32 + lane]);
            float4 v2 = __ldg(&h4[(size_t)s2 * 32 + lane]);
            float4 v3 = __ldg(&h4[(size_t)s3 * 32 + lane]);
            float f0 = __ldg(&rel[(size_t)r0 * 32 + lane]);
            float f1 = __ldg(&rel[(size_t)r1 * 32 + lane]);
            float f2 = __ldg(&rel[(size_t)r2 * 32 + lane]);
            float f3 = __ldg(&rel[(size_t)r3 * 32 + lane]);
            a.x += v0.x + v1.x + v2.x + v3.x;
            a.y += v0.y + v1.y + v2.y + v3.y;
            a.z += v0.z + v1.z + v2.z + v3.z;
            a.w += v0.w + v1.w + v2.w + v3.w;
            ra  += f0 + f1 + f2 + f3;
        }
        for (; i < cnt; i++){
            int s0 = __shfl_sync(FULLMASK, m.x, i);
            int r0 = __shfl_sync(FULLMASK, m.y, i);
            float4 v = __ldg(&h4[(size_t)s0 * 32 + lane]);
            a.x += v.x; a.y += v.y; a.z += v.z; a.w += v.w;
            ra += __ldg(&rel[(size_t)r0 * 32 + lane]);
        }
    }
    float inv = __ldg(&invdeg[w]);
    a.x *= inv; a.y *= inv; a.z *= inv; a.w *= inv;
    acch4[(size_t)w * 32 + lane] = a;
    accr[(size_t)w * 32 + lane] = ra * inv;
}

// ---------- input projection: h = relu([x, label_emb[label]] @ Win + b) ----------
#define IP_SMEM_FLOATS (20480 + 128 + 4 * 1288)
__global__ __launch_bounds__(512, 1)
void input_proj_kernel(const float* __restrict__ x, const int* __restrict__ label,
                       const float* __restrict__ label_emb, const float* __restrict__ Win,
                       const float* __restrict__ bin, float* __restrict__ hout){
    extern __shared__ float sm[];
    float* W_s = sm;                 // 160*128
    float* b_s = sm + 20480;         // 128
    int tid = threadIdx.x;
    int group = tid >> 7;
    int j = tid & 127;
    float* xs = sm + 20608 + group * 1288;  // 160*8 staging (+pad)

    for (int i = tid; i < 20480; i += 512) W_s[i] = Win[i];
    if (tid < 128) b_s[tid] = bin[tid];

    int gid = blockIdx.x * 4 + group;
    int ngroups = gridDim.x * 4;
    const int NBATCH = N_NODES / 8;  // 6250
    int iters = (NBATCH + ngroups - 1) / ngroups;

    for (int it = 0; it < iters; it++){
        int bi = gid + it * ngroups;
        bool valid = bi < NBATCH;
        int node0 = bi * 8;
        __syncthreads();
        if (valid){
            #pragma unroll
            for (int m = 0; m < 8; m++){
                int node = node0 + m;
                xs[j * 8 + m] = x[(size_t)node * 128 + j];
                if (j < 32){
                    int lab = __ldg(&label[node]);
                    xs[(128 + j) * 8 + m] = label_emb[(size_t)lab * 32 + j];
                }
            }
        }
        __syncthreads();
        if (valid){
            ull c0 = 0, c1 = 0, c2 = 0, c3 = 0;
            const ulonglong2* X2 = (const ulonglong2*)xs;
            #pragma unroll 4
            for (int k = 0; k < 160; k++){
                float w = W_s[k * 128 + j];
                ull w2 = pack2(w, w);
                ulonglong2 p = X2[2 * k], q = X2[2 * k + 1];
                c0 = fma2(w2, p.x, c0); c1 = fma2(w2, p.y, c1);
                c2 = fma2(w2, q.x, c2); c3 = fma2(w2, q.y, c3);
            }
            float bb = b_s[j];
            float v[8];
            unpack2(c0, v[0], v[1]); unpack2(c1, v[2], v[3]);
            unpack2(c2, v[4], v[5]); unpack2(c3, v[6], v[7]);
            #pragma unroll
            for (int m = 0; m < 8; m++)
                hout[(size_t)(node0 + m) * 128 + j] = fmaxf(v[m] + bb, 0.f);
        }
    }
}

// ---------- node update: h' = LN(relu(h@Ws + b + acc_h@Wn + acc_r@Wr)) ----------
// (inv_deg already folded into acc_h / acc_r by gather_kernel)
#define NU_WOFF 37248
#define NU_GRPF 2376
#define NU_SMEM_FLOATS (NU_WOFF + 4 * NU_GRPF)
__global__ __launch_bounds__(512, 1)
void node_update_kernel(const float* __restrict__ hin, const float* __restrict__ acch,
                        const float* __restrict__ accr,
                        const float* __restrict__ Wn, const float* __restrict__ Wr,
                        const float* __restrict__ Wself, const float* __restrict__ bias,
                        const float* __restrict__ lng, const float* __restrict__ lnb,
                        float* __restrict__ hout){
    extern __shared__ float sm[];
    float* Wn_s   = sm;             // 16384
    float* Wr_s   = sm + 16384;     // 4096
    float* Ws_s   = sm + 20480;     // 16384
    float* bias_s = sm + 36864;     // 128
    float* g_s    = sm + 36992;     // 128
    float* b_s    = sm + 37120;     // 128
    int tid = threadIdx.x;
    int group = tid >> 7;
    int j = tid & 127;
    int lane = tid & 31;
    int wig = (tid & 127) >> 5;
    float* grp = sm + NU_WOFF + group * NU_GRPF;
    float* hs  = grp;          // 1024: hs[k][m]
    float* as_ = grp + 1024;   // 1024
    float* rs  = grp + 2048;   // 256
    float* red = grp + 2304;   // 64

    for (int i = tid; i < 16384; i += 512){ Wn_s[i] = Wn[i]; Ws_s[i] = Wself[i]; }
    for (int i = tid; i < 4096; i += 512) Wr_s[i] = Wr[i];
    if (tid < 128){ bias_s[tid] = bias[tid]; g_s[tid] = lng[tid]; b_s[tid] = lnb[tid]; }

    int gid = blockIdx.x * 4 + group;
    int ngroups = gridDim.x * 4;
    const int NBATCH = N_NODES / 8;  // 6250
    int iters = (NBATCH + ngroups - 1) / ngroups;

    for (int it = 0; it < iters; it++){
        int bi = gid + it * ngroups;
        bool valid = bi < NBATCH;
        int node0 = bi * 8;
        __syncthreads();
        if (valid){
            #pragma unroll
            for (int m = 0; m < 8; m++){
                int node = node0 + m;
                hs[j * 8 + m]  = hin[(size_t)node * 128 + j];
                as_[j * 8 + m] = acch[(size_t)node * 128 + j];
            }
            #pragma unroll
            for (int t2 = j * 2; t2 < j * 2 + 2; t2++)
                rs[t2] = accr[(size_t)(node0 + (t2 & 7)) * 32 + (t2 >> 3)];
        }
        __syncthreads();
        float v[8];
        if (valid){
            ull c0 = 0, c1 = 0, c2 = 0, c3 = 0;
            const ulonglong2* A2 = (const ulonglong2*)as_;
            #pragma unroll 4
            for (int k = 0; k < 128; k++){
                float w = Wn_s[k * 128 + j];
                ull w2 = pack2(w, w);
                ulonglong2 p = A2[2 * k], q = A2[2 * k + 1];
                c0 = fma2(w2, p.x, c0); c1 = fma2(w2, p.y, c1);
                c2 = fma2(w2, q.x, c2); c3 = fma2(w2, q.y, c3);
            }
            const ulonglong2* R2 = (const ulonglong2*)rs;
            #pragma unroll 4
            for (int k = 0; k < 32; k++){
                float w = Wr_s[k * 128 + j];
                ull w2 = pack2(w, w);
                ulonglong2 p = R2[2 * k], q = R2[2 * k + 1];
                c0 = fma2(w2, p.x, c0); c1 = fma2(w2, p.y, c1);
                c2 = fma2(w2, q.x, c2); c3 = fma2(w2, q.y, c3);
            }
            const ulonglong2* H2 = (const ulonglong2*)hs;
            #pragma unroll 4
            for (int k = 0; k < 128; k++){
                float w = Ws_s[k * 128 + j];
                ull w2 = pack2(w, w);
                ulonglong2 p = H2[2 * k], q = H2[2 * k + 1];
                c0 = fma2(w2, p.x, c0); c1 = fma2(w2, p.y, c1);
                c2 = fma2(w2, q.x, c2); c3 = fma2(w2, q.y, c3);
            }
            float bb = bias_s[j];
            ull b2 = pack2(bb, bb);
            c0 = add2(c0, b2); c1 = add2(c1, b2); c2 = add2(c2, b2); c3 = add2(c3, b2);
            unpack2(c0, v[0], v[1]); unpack2(c1, v[2], v[3]);
            unpack2(c2, v[4], v[5]); unpack2(c3, v[6], v[7]);
            #pragma unroll
            for (int m = 0; m < 8; m++){
                v[m] = fmaxf(v[m], 0.f);
                float s = v[m], q2 = v[m] * v[m];
                #pragma unroll
                for (int o = 16; o > 0; o >>= 1){
                    s  += __shfl_xor_sync(FULLMASK, s, o);
                    q2 += __shfl_xor_sync(FULLMASK, q2, o);
                }
                if (lane == 0){ red[wig * 16 + m] = s; red[wig * 16 + 8 + m] = q2; }
            }
        }
        __syncthreads();
        if (valid){
            #pragma unroll
            for (int m = 0; m < 8; m++){
                float s  = red[m] + red[16 + m] + red[32 + m] + red[48 + m];
                float q2 = red[8 + m] + red[24 + m] + red[40 + m] + red[56 + m];
                float mean = s * (1.0f / 128.0f);
                float var = fmaxf(q2 * (1.0f / 128.0f) - mean * mean, 0.f);
                float rstd = rsqrtf(var + 1e-5f);
                hout[(size_t)(node0 + m) * 128 + j] = (v[m] - mean) * rstd * g_s[j] + b_s[j];
            }
        }
    }
}

extern "C" void kernel_launch(void* const* d_in, const int* in_sizes, int n_in,
                              void* d_out, int out_size){
    const float* x         = (const float*)d_in[0];
    const int*   label     = (const int*)d_in[1];
    const int*   ei        = (const int*)d_in[2];
    const int*   er        = (const int*)d_in[3];
    const float* label_emb = (const float*)d_in[4];
    const float* in_w      = (const float*)d_in[5];
    const float* in_b      = (const float*)d_in[6];
    const float* rel_emb   = (const float*)d_in[7];
    const float* wn        = (const float*)d_in[8];
    const float* wself     = (const float*)d_in[9];
    const float* bself     = (const float*)d_in[10];
    const float* wr        = (const float*)d_in[11];
    const float* lng       = (const float*)d_in[12];
    const float* lnb       = (const float*)d_in[13];

    float *h0, *h1, *acch, *accr, *invdeg;
    int *deg, *row, *cursor;
    int2 *edges;
    cudaGetSymbolAddress((void**)&h0, g_h0);
    cudaGetSymbolAddress((void**)&h1, g_h1);
    cudaGetSymbolAddress((void**)&acch, g_acch);
    cudaGetSymbolAddress((void**)&accr, g_accr);
    cudaGetSymbolAddress((void**)&deg, g_deg);
    cudaGetSymbolAddress((void**)&invdeg, g_invdeg);
    cudaGetSymbolAddress((void**)&row, g_row);
    cudaGetSymbolAddress((void**)&cursor, g_cursor);
    cudaGetSymbolAddress((void**)&edges, g_edges);

    int ip_smem = IP_SMEM_FLOATS * 4;
    int nu_smem = NU_SMEM_FLOATS * 4;
    cudaFuncSetAttribute(input_proj_kernel, cudaFuncAttributeMaxDynamicSharedMemorySize, ip_smem);
    cudaFuncSetAttribute(node_update_kernel, cudaFuncAttributeMaxDynamicSharedMemorySize, nu_smem);

    // CSR build
    zero_deg_kernel<<<(N_NODES + 255) / 256, 256>>>(deg);
    deg_kernel<<<1024, 256>>>(ei, deg);
    scan_kernel<<<1, 1024>>>(deg, row, cursor, invdeg);
    scatter_kernel<<<1024, 256>>>(ei, er, cursor, edges);

    // input projection
    input_proj_kernel<<<148, 512, ip_smem>>>(x, label, label_emb, in_w, in_b, h0);

    // layer 0
    gather_kernel<<<(N_NODES * 32 + 255) / 256, 256>>>(row, edges, invdeg,
                                                       (const float4*)h0, rel_emb,
                                                       (float4*)acch, accr);
    node_update_kernel<<<148, 512, nu_smem>>>(h0, acch, accr,
                                              wn, wr, wself, bself, lng, lnb, h1);

    // layer 1
    gather_kernel<<<(N_NODES * 32 + 255) / 256, 256>>>(row, edges, invdeg,
                                                       (const float4*)h1, rel_emb + 1024 * 32,
                                                       (float4*)acch, accr);
    node_update_kernel<<<148, 512, nu_smem>>>(h1, acch, accr,
                                              wn + 16384, wr + 4096, wself + 16384,
                                              bself + 128, lng + 128, lnb + 128,
                                              (float*)d_out);
}